// round 2
// baseline (speedup 1.0000x reference)
#include <cuda_runtime.h>
#include <cuda_bf16.h>
#include <math.h>
#include <stdint.h>
#include <stddef.h>

#define NN 65536
#define EE 1048576
#define FMAXV 3.402823466e38f

// ---------------- static device scratch (no allocations) ----------------
__device__ float g_e[(size_t)EE * 32];      // edge_attr @ W_edge^T (no bias)
__device__ float g_c[(size_t)EE * 128];     // e @ Wpre_edgepart
__device__ float g_a[(size_t)NN * 128];     // dst-side node pre-part
__device__ float g_b[(size_t)NN * 128];     // src-side node pre-part
__device__ float g_agg[(size_t)NN * 512];   // per node/tower: [mean|mx|mn|std] x32
__device__ float g_Z[(size_t)NN * 128];     // post-MLP output
__device__ float g_s1[NN];
__device__ float g_s2[NN];
__device__ int   g_cnt[NN];
__device__ int   g_fill[NN];
__device__ int   g_rowptr[NN + 1];
__device__ int   g_eid[EE];
__device__ float g_biasm[128];
__device__ float g_WedgeT[128 * 32];        // [k][f]
__device__ float g_WlinT[128 * 128];        // [k][c]
__device__ float g_avglog;

// ---------------- setup ----------------
__global__ void k_zero(void) {
    int i = blockIdx.x * 256 + threadIdx.x;
    if (i < NN) { g_cnt[i] = 0; g_fill[i] = 0; }
}

__global__ void k_prep(const float* __restrict__ W_edge, const float* __restrict__ W_lin,
                       const float* __restrict__ W_pre, const float* __restrict__ b_pre,
                       const float* __restrict__ b_edge) {
    int i = blockIdx.x * 256 + threadIdx.x;
    if (i < 128 * 32) {                      // WedgeT[k*32+f] = W_edge[f*128+k]
        int k = i >> 5, f = i & 31;
        g_WedgeT[i] = W_edge[f * 128 + k];
    }
    if (i < 128 * 128) {                     // WlinT[k*128+c] = W_lin[c*128+k]
        int k = i >> 7, c = i & 127;
        g_WlinT[i] = W_lin[c * 128 + k];
    }
    if (i < 128) {                           // biasm = b_pre + Wpre_e^T b_edge
        int t = i >> 5, g = i & 31;
        float s = b_pre[i];
        for (int j = 0; j < 32; j++)
            s += b_edge[j] * W_pre[t * 3072 + (64 + j) * 32 + g];
        g_biasm[i] = s;
    }
    if (i == 0) {                            // AVG_LOG in double, as reference
        const double cnts[6] = {108477.0, 299931.0, 180702.0, 10767.0, 3.0, 2.0};
        double num = 0.0, den = 0.0;
        for (int d = 0; d < 6; d++) { num += cnts[d] * log((double)(d + 1) + 1.0); den += cnts[d]; }
        g_avglog = (float)(num / den);
    }
}

// ---------------- CSR build ----------------
__global__ void k_hist(const int* __restrict__ dst) {
    int i = blockIdx.x * 256 + threadIdx.x;
    if (i < EE) atomicAdd(&g_cnt[dst[i]], 1);
}

__global__ void k_scan(void) {
    __shared__ int sh[1024];
    int t = threadIdx.x;
    int base = t * 64;
    int s = 0;
    for (int j = 0; j < 64; j++) s += g_cnt[base + j];
    sh[t] = s;
    __syncthreads();
    for (int off = 1; off < 1024; off <<= 1) {
        int v = (t >= off) ? sh[t - off] : 0;
        __syncthreads();
        sh[t] += v;
        __syncthreads();
    }
    int run = sh[t] - s;                     // exclusive
    for (int j = 0; j < 64; j++) {
        int c = g_cnt[base + j];
        g_rowptr[base + j] = run;
        run += c;
    }
    if (t == 1023) g_rowptr[NN] = sh[1023];
}

__global__ void k_scatter(const int* __restrict__ dst) {
    int i = blockIdx.x * 256 + threadIdx.x;
    if (i < EE) {
        int d = dst[i];
        int slot = g_rowptr[d] + atomicAdd(&g_fill[d], 1);
        g_eid[slot] = i;
    }
}

// ---------------- node pre-parts: a (dst rows of W_pre), b (src rows) ----------------
__global__ void k_ab(const float* __restrict__ x, const float* __restrict__ W_pre) {
    int i = blockIdx.x * 256 + threadIdx.x;
    if (i >= NN * 128) return;
    int n = i >> 7, ch = i & 127;
    int t = ch >> 5, g = ch & 31;
    const float* xr = x + (size_t)n * 128 + t * 32;
    const float* wa = W_pre + t * 3072 + g;        // rows 0..31
    const float* wb = wa + 1024;                   // rows 32..63
    float a = 0.f, b = 0.f;
#pragma unroll
    for (int f = 0; f < 32; f++) {
        float xv = __ldg(&xr[f]);
        a = fmaf(xv, __ldg(&wa[f * 32]), a);
        b = fmaf(xv, __ldg(&wb[f * 32]), b);
    }
    g_a[i] = a; g_b[i] = b;
}

// ---------------- e-GEMM: e[E,32] = edge_attr[E,128] @ WedgeT ----------------
__global__ __launch_bounds__(256) void k_egemm(const float* __restrict__ ea) {
    __shared__ float sA[256 * 36];
    __shared__ float sW[32 * 36];
    int r0b = blockIdx.x * 256;
    int tid = threadIdx.x;
    int c4 = (tid & 7) * 4;
    int rg = tid >> 3;
    float4 acc[8];
#pragma unroll
    for (int r = 0; r < 8; r++) acc[r] = make_float4(0.f, 0.f, 0.f, 0.f);

    for (int k0 = 0; k0 < 128; k0 += 32) {
        __syncthreads();
        for (int i = tid; i < 256 * 8; i += 256) {
            int r = i >> 3, kg = (i & 7) * 4;
            *(float4*)&sA[r * 36 + kg] = *(const float4*)&ea[(size_t)(r0b + r) * 128 + k0 + kg];
        }
        for (int i = tid; i < 32 * 8; i += 256) {
            int kk = i >> 3, fg = (i & 7) * 4;
            *(float4*)&sW[kk * 36 + fg] = *(const float4*)&g_WedgeT[(k0 + kk) * 32 + fg];
        }
        __syncthreads();
#pragma unroll
        for (int k4 = 0; k4 < 8; k4++) {
            float4 w0 = *(float4*)&sW[(k4 * 4 + 0) * 36 + c4];
            float4 w1 = *(float4*)&sW[(k4 * 4 + 1) * 36 + c4];
            float4 w2 = *(float4*)&sW[(k4 * 4 + 2) * 36 + c4];
            float4 w3 = *(float4*)&sW[(k4 * 4 + 3) * 36 + c4];
#pragma unroll
            for (int r = 0; r < 8; r++) {
                float4 a = *(float4*)&sA[(rg * 8 + r) * 36 + k4 * 4];
                acc[r].x = fmaf(a.x, w0.x, fmaf(a.y, w1.x, fmaf(a.z, w2.x, fmaf(a.w, w3.x, acc[r].x))));
                acc[r].y = fmaf(a.x, w0.y, fmaf(a.y, w1.y, fmaf(a.z, w2.y, fmaf(a.w, w3.y, acc[r].y))));
                acc[r].z = fmaf(a.x, w0.z, fmaf(a.y, w1.z, fmaf(a.z, w2.z, fmaf(a.w, w3.z, acc[r].z))));
                acc[r].w = fmaf(a.x, w0.w, fmaf(a.y, w1.w, fmaf(a.z, w2.w, fmaf(a.w, w3.w, acc[r].w))));
            }
        }
    }
#pragma unroll
    for (int r = 0; r < 8; r++) {
        int row = r0b + rg * 8 + r;
        *(float4*)&g_e[(size_t)row * 32 + c4] = acc[r];
    }
}

// ---------------- c-GEMM: c[E,128] = e[E,32] @ Wpre_edgepart ----------------
__global__ __launch_bounds__(256) void k_cgemm(const float* __restrict__ W_pre) {
    __shared__ float sA[64 * 36];
    __shared__ float sW[32 * 128];   // [j][o], o = t*32+g
    int r0b = blockIdx.x * 64;
    int tid = threadIdx.x;
    for (int i = tid; i < 32 * 32; i += 256) {
        int j = i >> 5, og = (i & 31) * 4;
        int t = og >> 5, g = og & 31;
        *(float4*)&sW[j * 128 + og] = *(const float4*)&W_pre[t * 3072 + (64 + j) * 32 + g];
    }
    for (int i = tid; i < 64 * 8; i += 256) {
        int r = i >> 3, kg = (i & 7) * 4;
        *(float4*)&sA[r * 36 + kg] = *(const float4*)&g_e[(size_t)(r0b + r) * 32 + kg];
    }
    __syncthreads();
    int c4 = (tid & 31) * 4;
    int rg = tid >> 5;
    float4 acc[8];
#pragma unroll
    for (int r = 0; r < 8; r++) acc[r] = make_float4(0.f, 0.f, 0.f, 0.f);
#pragma unroll
    for (int k4 = 0; k4 < 8; k4++) {
        float4 w0 = *(float4*)&sW[(k4 * 4 + 0) * 128 + c4];
        float4 w1 = *(float4*)&sW[(k4 * 4 + 1) * 128 + c4];
        float4 w2 = *(float4*)&sW[(k4 * 4 + 2) * 128 + c4];
        float4 w3 = *(float4*)&sW[(k4 * 4 + 3) * 128 + c4];
#pragma unroll
        for (int r = 0; r < 8; r++) {
            float4 a = *(float4*)&sA[(rg * 8 + r) * 36 + k4 * 4];
            acc[r].x = fmaf(a.x, w0.x, fmaf(a.y, w1.x, fmaf(a.z, w2.x, fmaf(a.w, w3.x, acc[r].x))));
            acc[r].y = fmaf(a.x, w0.y, fmaf(a.y, w1.y, fmaf(a.z, w2.y, fmaf(a.w, w3.y, acc[r].y))));
            acc[r].z = fmaf(a.x, w0.z, fmaf(a.y, w1.z, fmaf(a.z, w2.z, fmaf(a.w, w3.z, acc[r].z))));
            acc[r].w = fmaf(a.x, w0.w, fmaf(a.y, w1.w, fmaf(a.z, w2.w, fmaf(a.w, w3.w, acc[r].w))));
        }
    }
#pragma unroll
    for (int r = 0; r < 8; r++) {
        int row = r0b + rg * 8 + r;
        *(float4*)&g_c[(size_t)row * 128 + c4] = acc[r];
    }
}

// ---------------- aggregation: one warp per node (sorted edge list) ----------------
__global__ __launch_bounds__(256) void k_agg(const int* __restrict__ srcp) {
    __shared__ int s_eid[8][128];
    int w = threadIdx.x >> 5;
    int lane = threadIdx.x & 31;
    int n = blockIdx.x * 8 + w;
    if (n >= NN) return;
    int start = g_rowptr[n], end = g_rowptr[n + 1];
    int deg = end - start;
    int msort = deg < 128 ? deg : 128;

    for (int j = lane; j < msort; j += 32) s_eid[w][j] = g_eid[start + j];
    __syncwarp();
    for (int pass = 0; pass < msort; pass++) {         // odd-even sort (deterministic order)
        int off = pass & 1;
        for (int j = lane; 2 * j + 1 + off < msort; j += 32) {
            int i0 = 2 * j + off, i1 = i0 + 1;
            int a = s_eid[w][i0], b = s_eid[w][i1];
            if (a > b) { s_eid[w][i0] = b; s_eid[w][i1] = a; }
        }
        __syncwarp();
    }

    float4 base = *(const float4*)&g_a[(size_t)n * 128 + lane * 4];
    float4 bm   = *(const float4*)&g_biasm[lane * 4];
    base.x += bm.x; base.y += bm.y; base.z += bm.z; base.w += bm.w;

    float4 s  = make_float4(0.f, 0.f, 0.f, 0.f);
    float4 sq = make_float4(0.f, 0.f, 0.f, 0.f);
    float4 mx = make_float4(-FMAXV, -FMAXV, -FMAXV, -FMAXV);
    float4 mn = make_float4( FMAXV,  FMAXV,  FMAXV,  FMAXV);

    for (int sl = 0; sl < deg; sl++) {
        int eid = (sl < 128) ? s_eid[w][sl] : __ldg(&g_eid[start + sl]);
        int sn  = __ldg(&srcp[eid]);
        float4 c = *(const float4*)&g_c[(size_t)eid * 128 + lane * 4];
        float4 b = *(const float4*)&g_b[(size_t)sn * 128 + lane * 4];
        float m0 = base.x + b.x + c.x;
        float m1 = base.y + b.y + c.y;
        float m2 = base.z + b.z + c.z;
        float m3 = base.w + b.w + c.w;
        s.x += m0; s.y += m1; s.z += m2; s.w += m3;
        sq.x = fmaf(m0, m0, sq.x); sq.y = fmaf(m1, m1, sq.y);
        sq.z = fmaf(m2, m2, sq.z); sq.w = fmaf(m3, m3, sq.w);
        mx.x = fmaxf(mx.x, m0); mx.y = fmaxf(mx.y, m1); mx.z = fmaxf(mx.z, m2); mx.w = fmaxf(mx.w, m3);
        mn.x = fminf(mn.x, m0); mn.y = fminf(mn.y, m1); mn.z = fminf(mn.z, m2); mn.w = fminf(mn.w, m3);
    }
    if (deg == 0) {
        mx = make_float4(0.f, 0.f, 0.f, 0.f);
        mn = make_float4(0.f, 0.f, 0.f, 0.f);
    }
    float cs = (float)(deg > 0 ? deg : 1);
    float inv = 1.0f / cs;
    float4 mean = make_float4(s.x * inv, s.y * inv, s.z * inv, s.w * inv);
    float4 msq  = make_float4(sq.x * inv, sq.y * inv, sq.z * inv, sq.w * inv);
    float4 sd;
    sd.x = sqrtf(fmaxf(msq.x - mean.x * mean.x, 0.f) + 1e-5f);
    sd.y = sqrtf(fmaxf(msq.y - mean.y * mean.y, 0.f) + 1e-5f);
    sd.z = sqrtf(fmaxf(msq.z - mean.z * mean.z, 0.f) + 1e-5f);
    sd.w = sqrtf(fmaxf(msq.w - mean.w * mean.w, 0.f) + 1e-5f);

    int t = (lane * 4) >> 5, g0 = (lane * 4) & 31;
    float* aggp = &g_agg[(size_t)n * 512 + t * 128 + g0];
    *(float4*)&aggp[0]  = mean;
    *(float4*)&aggp[32] = mx;
    *(float4*)&aggp[64] = mn;
    *(float4*)&aggp[96] = sd;

    if (lane == 0) {
        float avg = g_avglog;
        float logd = logf((float)deg + 1.0f);
        g_s1[n] = logd / avg;
        g_s2[n] = (deg == 0) ? 1.0f : (avg / logd);
    }
}

// ---------------- post-MLP: y = xt@W0 + agg@W1 + s1*(agg@W2) + s2*(agg@W3) + b ----------------
__global__ __launch_bounds__(256) void k_post(const float* __restrict__ x,
                                              const float* __restrict__ W_post,
                                              const float* __restrict__ b_post) {
    __shared__ float s_w0[32 * 32];
    __shared__ float s_w1[32 * 32];
    __shared__ float s_w2[32 * 32];
    __shared__ float s_w3[32 * 32];
    __shared__ float s_xt[64 * 32];
    __shared__ float s_ag[64 * 32];
    __shared__ float s_c1[64], s_c2[64];

    int t  = blockIdx.y;
    int n0 = blockIdx.x * 64;
    int tid = threadIdx.x;
    int g = tid & 31;
    int rslot = tid >> 5;
    const float* Wt = W_post + (size_t)t * 416 * 32;

    // stage W0 + xt + scalers once
    for (int i = tid; i < 32 * 32; i += 256) s_w0[i] = Wt[i];
    for (int i = tid; i < 64 * 32; i += 256) {
        int r = i >> 5, f = i & 31;
        s_xt[i] = x[(size_t)(n0 + r) * 128 + t * 32 + f];
    }
    if (tid < 64) { s_c1[tid] = g_s1[n0 + tid]; s_c2[tid] = g_s2[n0 + tid]; }
    __syncthreads();

    float acc1[8], acc2[8], acc3[8];
#pragma unroll
    for (int r = 0; r < 8; r++) { acc1[r] = 0.f; acc2[r] = 0.f; acc3[r] = 0.f; }

    // xt @ W0 into acc1
#pragma unroll 4
    for (int f = 0; f < 32; f++) {
        float w0 = s_w0[f * 32 + g];
#pragma unroll
        for (int r = 0; r < 8; r++)
            acc1[r] = fmaf(s_xt[(rslot * 8 + r) * 32 + f], w0, acc1[r]);
    }

    for (int kt = 0; kt < 4; kt++) {
        int k0 = kt * 32;
        __syncthreads();
        for (int i = tid; i < 32 * 32; i += 256) {
            int kk = i >> 5, gg = i & 31;
            s_w1[i] = Wt[(32 + k0 + kk) * 32 + gg];
            s_w2[i] = Wt[(160 + k0 + kk) * 32 + gg];
            s_w3[i] = Wt[(288 + k0 + kk) * 32 + gg];
        }
        for (int i = tid; i < 64 * 32; i += 256) {
            int r = i >> 5, kk = i & 31;
            s_ag[i] = g_agg[(size_t)(n0 + r) * 512 + t * 128 + k0 + kk];
        }
        __syncthreads();
#pragma unroll 4
        for (int k = 0; k < 32; k++) {
            float w1 = s_w1[k * 32 + g];
            float w2 = s_w2[k * 32 + g];
            float w3 = s_w3[k * 32 + g];
#pragma unroll
            for (int r = 0; r < 8; r++) {
                float a = s_ag[(rslot * 8 + r) * 32 + k];
                acc1[r] = fmaf(a, w1, acc1[r]);
                acc2[r] = fmaf(a, w2, acc2[r]);
                acc3[r] = fmaf(a, w3, acc3[r]);
            }
        }
    }

    float bp = b_post[t * 32 + g];
#pragma unroll
    for (int r = 0; r < 8; r++) {
        int row = rslot * 8 + r;
        float y = acc1[r] + s_c1[row] * acc2[r] + s_c2[row] * acc3[r] + bp;
        g_Z[(size_t)(n0 + row) * 128 + t * 32 + g] = y;
    }
}

// ---------------- final: out = Z @ W_lin^T + b_lin + x ----------------
__global__ __launch_bounds__(256) void k_final(const float* __restrict__ x,
                                               const float* __restrict__ b_lin,
                                               float* __restrict__ out) {
    __shared__ float sA[64 * 36];
    __shared__ float sW[32 * 128];
    int r0b = blockIdx.x * 64;
    int tid = threadIdx.x;
    int c4 = (tid & 31) * 4;
    int rg = tid >> 5;
    float4 acc[8];
#pragma unroll
    for (int r = 0; r < 8; r++) acc[r] = make_float4(0.f, 0.f, 0.f, 0.f);

    for (int k0 = 0; k0 < 128; k0 += 32) {
        __syncthreads();
        for (int i = tid; i < 64 * 8; i += 256) {
            int r = i >> 3, kg = (i & 7) * 4;
            *(float4*)&sA[r * 36 + kg] = *(const float4*)&g_Z[(size_t)(r0b + r) * 128 + k0 + kg];
        }
        for (int i = tid; i < 32 * 32; i += 256) {
            int kk = i >> 5, cg = (i & 31) * 4;
            *(float4*)&sW[kk * 128 + cg] = *(const float4*)&g_WlinT[(k0 + kk) * 128 + cg];
        }
        __syncthreads();
#pragma unroll
        for (int k4 = 0; k4 < 8; k4++) {
            float4 w0 = *(float4*)&sW[(k4 * 4 + 0) * 128 + c4];
            float4 w1 = *(float4*)&sW[(k4 * 4 + 1) * 128 + c4];
            float4 w2 = *(float4*)&sW[(k4 * 4 + 2) * 128 + c4];
            float4 w3 = *(float4*)&sW[(k4 * 4 + 3) * 128 + c4];
#pragma unroll
            for (int r = 0; r < 8; r++) {
                float4 a = *(float4*)&sA[(rg * 8 + r) * 36 + k4 * 4];
                acc[r].x = fmaf(a.x, w0.x, fmaf(a.y, w1.x, fmaf(a.z, w2.x, fmaf(a.w, w3.x, acc[r].x))));
                acc[r].y = fmaf(a.x, w0.y, fmaf(a.y, w1.y, fmaf(a.z, w2.y, fmaf(a.w, w3.y, acc[r].y))));
                acc[r].z = fmaf(a.x, w0.z, fmaf(a.y, w1.z, fmaf(a.z, w2.z, fmaf(a.w, w3.z, acc[r].z))));
                acc[r].w = fmaf(a.x, w0.w, fmaf(a.y, w1.w, fmaf(a.z, w2.w, fmaf(a.w, w3.w, acc[r].w))));
            }
        }
    }
#pragma unroll
    for (int r = 0; r < 8; r++) {
        int row = r0b + rg * 8 + r;
        float4 bl = *(const float4*)&b_lin[c4];
        float4 xr = *(const float4*)&x[(size_t)row * 128 + c4];
        acc[r].x += bl.x + xr.x;
        acc[r].y += bl.y + xr.y;
        acc[r].z += bl.z + xr.z;
        acc[r].w += bl.w + xr.w;
        *(float4*)&out[(size_t)row * 128 + c4] = acc[r];
    }
}

// ---------------- launch ----------------
extern "C" void kernel_launch(void* const* d_in, const int* in_sizes, int n_in,
                              void* d_out, int out_size) {
    const float* x         = (const float*)d_in[0];
    const float* edge_attr = (const float*)d_in[1];
    const int*   edge_idx  = (const int*)d_in[2];
    const float* W_edge    = (const float*)d_in[3];
    const float* b_edge    = (const float*)d_in[4];
    const float* W_pre     = (const float*)d_in[5];
    const float* b_pre     = (const float*)d_in[6];
    const float* W_post    = (const float*)d_in[7];
    const float* b_post    = (const float*)d_in[8];
    const float* W_lin     = (const float*)d_in[9];
    const float* b_lin     = (const float*)d_in[10];
    float* out = (float*)d_out;

    const int* srcp = edge_idx;
    const int* dstp = edge_idx + EE;

    k_zero<<<NN / 256, 256>>>();
    k_prep<<<64, 256>>>(W_edge, W_lin, W_pre, b_pre, b_edge);
    k_hist<<<EE / 256, 256>>>(dstp);
    k_scan<<<1, 1024>>>();
    k_scatter<<<EE / 256, 256>>>(dstp);
    k_ab<<<(NN * 128) / 256, 256>>>(x, W_pre);
    k_egemm<<<EE / 256, 256>>>(edge_attr);
    k_cgemm<<<EE / 64, 256>>>(W_pre);
    k_agg<<<NN / 8, 256>>>(srcp);
    k_post<<<dim3(NN / 64, 4), 256>>>(x, W_post, b_post);
    k_final<<<NN / 64, 256>>>(x, b_lin, out);
}